// round 4
// baseline (speedup 1.0000x reference)
#include <cuda_runtime.h>
#include <cuda.h>
#include <cuda_fp16.h>
#include <cstdint>

#define NN    8192
#define FX    48
#define FRW   16
#define IND   64

#define TILE_M      128
#define TILE_N      64
#define KT          32                  // fp32 K per stage (=128B rows)
#define STAGES      3
#define KITERS      (NN / KT)           // 256

// per-stage smem layout (bytes)
#define A32_OFF     0                   // [128][32] f32 = 16384
#define B32_OFF     16384               // [64][32] f32  = 8192
#define AH_OFF      24576               // [128][40] f16 = 10240 (pad 40 for bank-free)
#define AL_OFF      34816               // [128][40] f16
#define BH_OFF      45056               // [64][40] f16 = 5120
#define BL_OFF      50176               // [64][40] f16
#define STAGE_BYTES 55296
#define TMA_BYTES   24576               // A32 + B32 per stage

#define GEMM_SMEM   (1024 + 1024 + STAGES * STAGE_BYTES)   // align slack + header + stages
#define MLP_SMEM    ((8192 + 8192 + 128 + 64) * 4)

// Scratch (allocation-free rule: __device__ globals)
__device__ __align__(1024) float g_Xt[IND * NN];       // X^T  [64][8192]
__device__ __align__(1024) float g_Y[3 * NN * IND];    // hopk @ X  [3][8192][64]

// ------------------------------- PTX helpers -------------------------------
__device__ __forceinline__ uint32_t smem_u32(const void* p) {
    uint32_t a;
    asm("{ .reg .u64 t; cvta.to.shared.u64 t, %1; cvt.u32.u64 %0, t; }" : "=r"(a) : "l"(p));
    return a;
}

#define MBAR_INIT(a, c) \
    asm volatile("mbarrier.init.shared.b64 [%0], %1;" :: "r"(a), "r"((uint32_t)(c)) : "memory")
#define MBAR_EXPECT(a, b) \
    asm volatile("mbarrier.arrive.expect_tx.shared.b64 _, [%0], %1;" :: "r"(a), "r"((uint32_t)(b)) : "memory")
#define MBAR_WAIT(addr, ph) do {                                                   \
    uint32_t _m = (addr); uint32_t _p = (uint32_t)(ph); uint32_t _d;               \
    asm volatile("{\n\t.reg .pred p;\n\t"                                          \
        "mbarrier.try_wait.parity.acquire.cta.shared::cta.b64 p, [%1], %2;\n\t"    \
        "selp.b32 %0, 1, 0, p;\n\t}"                                               \
        : "=r"(_d) : "r"(_m), "r"(_p) : "memory");                                 \
    if (!_d) {                                                                     \
        asm volatile("{\n\t.reg .pred P1;\n\t"                                     \
            "WL%=:\n\t"                                                            \
            "mbarrier.try_wait.parity.acquire.cta.shared::cta.b64 P1, [%0], %1, 0x989680;\n\t" \
            "@P1 bra.uni WD%=;\n\t"                                                \
            "bra.uni WL%=;\n\t"                                                    \
            "WD%=:\n\t}"                                                           \
            :: "r"(_m), "r"(_p) : "memory");                                       \
    } } while (0)

__device__ __forceinline__ void tma2d(uint32_t dst, const CUtensorMap* m, int x, int y, uint32_t bar) {
    asm volatile(
        "cp.async.bulk.tensor.2d.shared::cta.global.tile.mbarrier::complete_tx::bytes "
        "[%0], [%1, {%2, %3}], [%4];"
        :: "r"(dst), "l"(m), "r"(x), "r"(y), "r"(bar) : "memory");
}

#define LDSM_X4(r0, r1, r2, r3, addr) \
    asm volatile("ldmatrix.sync.aligned.m8n8.x4.shared.b16 {%0,%1,%2,%3}, [%4];" \
        : "=r"(r0), "=r"(r1), "=r"(r2), "=r"(r3) : "r"(addr))

__device__ __forceinline__ void mma16816(float* d, const uint32_t* a, uint32_t b0, uint32_t b1) {
    asm volatile(
        "mma.sync.aligned.m16n8k16.row.col.f32.f16.f16.f32 "
        "{%0,%1,%2,%3}, {%4,%5,%6,%7}, {%8,%9}, {%0,%1,%2,%3};"
        : "+f"(d[0]), "+f"(d[1]), "+f"(d[2]), "+f"(d[3])
        : "r"(a[0]), "r"(a[1]), "r"(a[2]), "r"(a[3]), "r"(b0), "r"(b1));
}

__device__ __forceinline__ uint32_t pack_h2(float a, float b) {
    __half2 h = __halves2half2(__float2half_rn(a), __float2half_rn(b));
    return *reinterpret_cast<uint32_t*>(&h);
}

// ---------------- Kernel A: X^T build + zero out ----------------
__global__ __launch_bounds__(256) void prep_kernel(const float* __restrict__ x,
                                                   const float* __restrict__ wf,
                                                   float* __restrict__ out) {
    int idx = blockIdx.x * 256 + threadIdx.x;      // 0 .. 524287
    int n  = idx >> 13;       // feature 0..63
    int kk = idx & (NN - 1);  // node
    g_Xt[idx] = (n < FX) ? x[kk * FX + n] : wf[kk * FRW + (n - FX)];
    out[idx] = 0.0f;
}

// ---------------- Kernel B: Y_hop = hop @ X  (fp16-split mma.sync) ----------------
__global__ void __launch_bounds__(256, 1)
gemm_hops(const __grid_constant__ CUtensorMap tmA1,
          const __grid_constant__ CUtensorMap tmA2,
          const __grid_constant__ CUtensorMap tmA3,
          const __grid_constant__ CUtensorMap tmB) {
    extern __shared__ char smem_raw[];
    const uint32_t sb0 = smem_u32(smem_raw);
    const uint32_t sb  = (sb0 + 1023u) & ~1023u;       // 1024-aligned
    char* base = smem_raw + (sb - sb0);

    const int tid  = threadIdx.x;
    const int lane = tid & 31;
    const int wid  = tid >> 5;
    const int wm   = wid & 3;          // M warp 0..3 (32 rows each)
    const int wn   = wid >> 2;         // N warp 0..1 (32 cols each)
    const int gid  = lane >> 2;
    const int tg   = lane & 3;

    const int hop  = blockIdx.y;
    const int row0 = blockIdx.x * TILE_M;
    const CUtensorMap* tmA = (hop == 0) ? &tmA1 : ((hop == 1) ? &tmA2 : &tmA3);

    const uint32_t mb   = sb;           // 3 x 8B full barriers
    const uint32_t DATA = sb + 1024;

    if (tid == 0) {
#pragma unroll
        for (int s = 0; s < STAGES; s++) MBAR_INIT(mb + 8 * s, 1);
        asm volatile("fence.proxy.async.shared::cta;" ::: "memory");
    }
    __syncthreads();

    // Prologue: fill all stages
    if (tid == 0) {
#pragma unroll
        for (int s = 0; s < STAGES; s++) {
            MBAR_EXPECT(mb + 8 * s, TMA_BYTES);
            tma2d(DATA + s * STAGE_BYTES + A32_OFF, tmA, s * KT, row0, mb + 8 * s);
            tma2d(DATA + s * STAGE_BYTES + B32_OFF, &tmB, s * KT, 0,   mb + 8 * s);
        }
    }

    float acc[2][4][4];
#pragma unroll
    for (int mt = 0; mt < 2; mt++)
#pragma unroll
        for (int nt = 0; nt < 4; nt++)
#pragma unroll
            for (int r = 0; r < 4; r++) acc[mt][nt][r] = 0.0f;

    // ldmatrix per-thread address components (within a stage's AH/AL buffer)
    const int j     = lane >> 3;                 // 0..3 (8x8 matrix id)
    const int lm_m  = ((j & 1) << 3) + (lane & 7);
    const int lm_k  = (j >> 1) << 3;

    int s = 0, ph = 0;
    for (int i = 0; i < KITERS; i++) {
        const uint32_t stg = DATA + s * STAGE_BYTES;
        char* stgp = base + 1024 + s * STAGE_BYTES;

        MBAR_WAIT(mb + 8 * s, ph);

        // ---- convert fp32 -> fp16 hi/lo ----
        {
            const float4* a32 = (const float4*)(stgp + A32_OFF);   // 1024 float4
            const float4* b32 = (const float4*)(stgp + B32_OFF);   // 512 float4
            __half* ah = (__half*)(stgp + AH_OFF);
            __half* al = (__half*)(stgp + AL_OFF);
            __half* bh = (__half*)(stgp + BH_OFF);
            __half* bl = (__half*)(stgp + BL_OFF);
#pragma unroll
            for (int t = 0; t < 4; t++) {
                int idx = tid + t * 256;
                float4 v = a32[idx];
                int m = idx >> 3, kg = idx & 7;
                float hx = __half2float(__float2half_rn(v.x));
                float hy = __half2float(__float2half_rn(v.y));
                float hz = __half2float(__float2half_rn(v.z));
                float hw = __half2float(__float2half_rn(v.w));
                uint2 hi = { pack_h2(v.x, v.y), pack_h2(v.z, v.w) };
                uint2 lo = { pack_h2(v.x - hx, v.y - hy), pack_h2(v.z - hz, v.w - hw) };
                *(uint2*)(ah + m * 40 + kg * 4) = hi;
                *(uint2*)(al + m * 40 + kg * 4) = lo;
            }
#pragma unroll
            for (int t = 0; t < 2; t++) {
                int idx = tid + t * 256;
                float4 v = b32[idx];
                int n = idx >> 3, kg = idx & 7;
                float hx = __half2float(__float2half_rn(v.x));
                float hy = __half2float(__float2half_rn(v.y));
                float hz = __half2float(__float2half_rn(v.z));
                float hw = __half2float(__float2half_rn(v.w));
                uint2 hi = { pack_h2(v.x, v.y), pack_h2(v.z, v.w) };
                uint2 lo = { pack_h2(v.x - hx, v.y - hy), pack_h2(v.z - hz, v.w - hw) };
                *(uint2*)(bh + n * 40 + kg * 4) = hi;
                *(uint2*)(bl + n * 40 + kg * 4) = lo;
            }
        }
        __syncthreads();   // conversions visible; fp32 stage free; mma(i-1) done by all

        // refill this stage for iteration i+STAGES
        if (tid == 0 && i + STAGES < KITERS) {
            MBAR_EXPECT(mb + 8 * s, TMA_BYTES);
            tma2d(stg + A32_OFF, tmA, (i + STAGES) * KT, row0, mb + 8 * s);
            tma2d(stg + B32_OFF, &tmB, (i + STAGES) * KT, 0,   mb + 8 * s);
        }

        // ---- mma: 2 ksteps of 16 ----
#pragma unroll
        for (int ks = 0; ks < 2; ks++) {
            const int kst = ks * 16;
            uint32_t ahf[2][4], alf[2][4];
#pragma unroll
            for (int mt = 0; mt < 2; mt++) {
                int mrow = wm * 32 + mt * 16 + lm_m;
                uint32_t addr_h = stg + AH_OFF + (uint32_t)(mrow * 40 + kst + lm_k) * 2;
                uint32_t addr_l = stg + AL_OFF + (uint32_t)(mrow * 40 + kst + lm_k) * 2;
                LDSM_X4(ahf[mt][0], ahf[mt][1], ahf[mt][2], ahf[mt][3], addr_h);
                LDSM_X4(alf[mt][0], alf[mt][1], alf[mt][2], alf[mt][3], addr_l);
            }
            uint32_t bhf[4][2], blf[4][2];
#pragma unroll
            for (int nt = 0; nt < 4; nt++) {
                int n = wn * 32 + nt * 8 + gid;
                const __half* bh = (const __half*)(stgp + BH_OFF) + n * 40 + kst + tg * 2;
                const __half* bl = (const __half*)(stgp + BL_OFF) + n * 40 + kst + tg * 2;
                bhf[nt][0] = *(const uint32_t*)bh;
                bhf[nt][1] = *(const uint32_t*)(bh + 8);
                blf[nt][0] = *(const uint32_t*)bl;
                blf[nt][1] = *(const uint32_t*)(bl + 8);
            }
#pragma unroll
            for (int mt = 0; mt < 2; mt++)
#pragma unroll
                for (int nt = 0; nt < 4; nt++) {
                    mma16816(acc[mt][nt], ahf[mt], bhf[nt][0], bhf[nt][1]);
                    mma16816(acc[mt][nt], ahf[mt], blf[nt][0], blf[nt][1]);
                    mma16816(acc[mt][nt], alf[mt], bhf[nt][0], bhf[nt][1]);
                }
        }

        if (++s == STAGES) { s = 0; ph ^= 1; }
    }

    // ---- epilogue: write Y tile ----
    float* Y = &g_Y[(size_t)hop * NN * IND];
#pragma unroll
    for (int mt = 0; mt < 2; mt++) {
        int r0 = row0 + wm * 32 + mt * 16 + gid;
#pragma unroll
        for (int nt = 0; nt < 4; nt++) {
            int c = wn * 32 + nt * 8 + tg * 2;
            *(float2*)&Y[(size_t)r0 * IND + c]       = make_float2(acc[mt][nt][0], acc[mt][nt][1]);
            *(float2*)&Y[(size_t)(r0 + 8) * IND + c] = make_float2(acc[mt][nt][2], acc[mt][nt][3]);
        }
    }
}

// ---------------- Kernel C: 4 parallel MLPs + sum ----------------
__global__ void __launch_bounds__(128) mlp_kernel(
    const float* __restrict__ x, const float* __restrict__ wf,
    const float* __restrict__ W1, const float* __restrict__ b1,
    const float* __restrict__ W2, const float* __restrict__ b2,
    float* __restrict__ out) {
    extern __shared__ float sm[];
    float* W1t = sm;            // [128][64]  (transposed: [h][f])
    float* W2s = sm + 8192;     // [128][64]
    float* b1s = sm + 16384;    // 128
    float* b2s = sm + 16512;    // 64

    const int k = blockIdx.y;
    const int tid = threadIdx.x;
    const float* W1g = W1 + k * 8192;
    const float* W2g = W2 + k * 8192;

    for (int idx = tid; idx < 8192; idx += 128) {
        int f = idx >> 7, h = idx & 127;
        W1t[h * 64 + f] = W1g[idx];      // W1g layout [f][h]
        W2s[idx] = W2g[idx];             // [h][o], o contiguous
    }
    b1s[tid] = b1[k * 128 + tid];
    if (tid < 64) b2s[tid] = b2[k * 64 + tid];
    __syncthreads();

    const int node = blockIdx.x * 128 + tid;
    float in_r[64];
    if (k == 0) {
#pragma unroll
        for (int f = 0; f < FX; f += 4)
            *(float4*)&in_r[f] = *(const float4*)&x[(size_t)node * FX + f];
#pragma unroll
        for (int f = 0; f < FRW; f += 4)
            *(float4*)&in_r[FX + f] = *(const float4*)&wf[(size_t)node * FRW + f];
    } else {
        const float4* yp = (const float4*)&g_Y[(((size_t)(k - 1)) * NN + node) * IND];
#pragma unroll
        for (int f = 0; f < 16; f++) *(float4*)&in_r[4 * f] = yp[f];
    }

    float acc[64];
#pragma unroll
    for (int o = 0; o < 64; o++) acc[o] = b2s[o];

#pragma unroll 2
    for (int hh = 0; hh < 128; hh++) {
        const float4* w1v = (const float4*)(W1t + hh * 64);
        float h0 = b1s[hh], h1 = 0.f;
#pragma unroll
        for (int f = 0; f < 16; f += 2) {
            float4 wa = w1v[f], wb = w1v[f + 1];
            h0 = fmaf(in_r[4*f+0], wa.x, h0); h1 = fmaf(in_r[4*f+1], wa.y, h1);
            h0 = fmaf(in_r[4*f+2], wa.z, h0); h1 = fmaf(in_r[4*f+3], wa.w, h1);
            h0 = fmaf(in_r[4*f+4], wb.x, h0); h1 = fmaf(in_r[4*f+5], wb.y, h1);
            h0 = fmaf(in_r[4*f+6], wb.z, h0); h1 = fmaf(in_r[4*f+7], wb.w, h1);
        }
        float h = fmaxf(h0 + h1, 0.0f);
        const float4* w2v = (const float4*)(W2s + hh * 64);
#pragma unroll
        for (int o = 0; o < 16; o++) {
            float4 w = w2v[o];
            acc[4*o+0] = fmaf(h, w.x, acc[4*o+0]);
            acc[4*o+1] = fmaf(h, w.y, acc[4*o+1]);
            acc[4*o+2] = fmaf(h, w.z, acc[4*o+2]);
            acc[4*o+3] = fmaf(h, w.w, acc[4*o+3]);
        }
    }

    float* op = out + (size_t)node * 64;
#pragma unroll
    for (int o = 0; o < 64; o++) atomicAdd(op + o, acc[o]);
}

// ------------------------------- host -------------------------------
typedef CUresult (*EncodeFn)(CUtensorMap*, CUtensorMapDataType, cuuint32_t, void*,
                             const cuuint64_t*, const cuuint64_t*, const cuuint32_t*,
                             const cuuint32_t*, CUtensorMapInterleave, CUtensorMapSwizzle,
                             CUtensorMapL2promotion, CUtensorMapFloatOOBfill);

static void make_map_2d(EncodeFn enc, CUtensorMap* m, const void* ptr,
                        uint64_t d0, uint64_t d1, uint32_t b0, uint32_t b1) {
    cuuint64_t dims[2]    = {d0, d1};
    cuuint64_t strides[1] = {d0 * sizeof(float)};
    cuuint32_t box[2]     = {b0, b1};
    cuuint32_t es[2]      = {1, 1};
    enc(m, CU_TENSOR_MAP_DATA_TYPE_FLOAT32, 2, (void*)ptr, dims, strides, box, es,
        CU_TENSOR_MAP_INTERLEAVE_NONE, CU_TENSOR_MAP_SWIZZLE_NONE,
        CU_TENSOR_MAP_L2_PROMOTION_L2_128B, CU_TENSOR_MAP_FLOAT_OOB_FILL_NONE);
}

extern "C" void kernel_launch(void* const* d_in, const int* in_sizes, int n_in,
                              void* d_out, int out_size) {
    const float* x    = (const float*)d_in[0];
    const float* wf   = (const float*)d_in[1];
    const float* hop1 = (const float*)d_in[2];
    const float* hop2 = (const float*)d_in[3];
    const float* hop3 = (const float*)d_in[4];
    const float* W1   = (const float*)d_in[5];
    const float* b1   = (const float*)d_in[6];
    const float* W2   = (const float*)d_in[7];
    const float* b2   = (const float*)d_in[8];
    float* out = (float*)d_out;

    void* fn = nullptr;
    cudaDriverEntryPointQueryResult qr;
    cudaGetDriverEntryPointByVersion("cuTensorMapEncodeTiled", &fn, 12000,
                                     cudaEnableDefault, &qr);
    EncodeFn enc = (EncodeFn)fn;

    void* xt_ptr = nullptr;
    cudaGetSymbolAddress(&xt_ptr, g_Xt);

    CUtensorMap tmA1, tmA2, tmA3, tmB;
    make_map_2d(enc, &tmA1, hop1, NN, NN, KT, TILE_M);
    make_map_2d(enc, &tmA2, hop2, NN, NN, KT, TILE_M);
    make_map_2d(enc, &tmA3, hop3, NN, NN, KT, TILE_M);
    make_map_2d(enc, &tmB, xt_ptr, NN, IND, KT, IND);

    cudaFuncSetAttribute(gemm_hops, cudaFuncAttributeMaxDynamicSharedMemorySize, GEMM_SMEM);
    cudaFuncSetAttribute(mlp_kernel, cudaFuncAttributeMaxDynamicSharedMemorySize, MLP_SMEM);

    prep_kernel<<<(NN * IND) / 256, 256>>>(x, wf, out);
    gemm_hops<<<dim3(NN / TILE_M, 3), 256, GEMM_SMEM>>>(tmA1, tmA2, tmA3, tmB);
    mlp_kernel<<<dim3(NN / 128, 4), 128, MLP_SMEM>>>(x, wf, W1, b1, W2, b2, out);
}